// round 3
// baseline (speedup 1.0000x reference)
#include <cuda_runtime.h>
#include <cuda_bf16.h>
#include <cstdint>

// Problem constants
#define DIMK   512
#define NCODE  8192
#define NTOK   16384           // B*N = 4*4096
#define QELEMS (NTOK * DIMK)   // 8388608

// ---------------- scratch (no allocations allowed) ----------------
__device__ float g_implicit[(size_t)NCODE * DIMK];  // 16 MB
__device__ float g_cnorm[NCODE];
__device__ int   g_indices[NTOK];
__device__ float g_partial[NTOK];

// packed fp32x2 FMA (FFMA2) — sm_103a only via PTX
__device__ __forceinline__ void fma2(float2 &d, const float2 &a, const float2 &b) {
    asm("fma.rn.f32x2 %0, %1, %2, %0;"
        : "+l"(reinterpret_cast<unsigned long long &>(d))
        : "l"(reinterpret_cast<const unsigned long long &>(a)),
          "l"(reinterpret_cast<const unsigned long long &>(b)));
}

// =====================================================================
// Kernel 1: implicit[c,d] = sum_k codebook[c,k] * W[d,k]
// 128x128 tile, BK=8, 256 threads, 8x8 per thread (f32x2 packed)
// grid (NCODE/128, DIMK/128)
// =====================================================================
__global__ __launch_bounds__(256, 2)
void implicit_gemm_kernel(const float* __restrict__ CB, const float* __restrict__ W) {
    __shared__ float As[8][132];
    __shared__ float Bs[8][132];

    const int tid = threadIdx.x;
    const int tx = tid & 15, ty = tid >> 4;
    const int row0 = blockIdx.x * 128;   // code rows
    const int col0 = blockIdx.y * 128;   // d cols

    const int lrow = tid >> 1;
    const int lkq  = (tid & 1) * 4;

    const float* abase = CB + (size_t)(row0 + lrow) * DIMK + lkq;
    const float* bbase = W  + (size_t)(col0 + lrow) * DIMK + lkq;

    float2 acc[8][4];
#pragma unroll
    for (int i = 0; i < 8; i++)
#pragma unroll
        for (int j = 0; j < 4; j++) acc[i][j] = make_float2(0.f, 0.f);

    for (int kt = 0; kt < DIMK / 8; kt++) {
        float4 av = *(const float4*)(abase + kt * 8);
        float4 bv = *(const float4*)(bbase + kt * 8);
        __syncthreads();
        As[lkq + 0][lrow] = av.x; As[lkq + 1][lrow] = av.y;
        As[lkq + 2][lrow] = av.z; As[lkq + 3][lrow] = av.w;
        Bs[lkq + 0][lrow] = bv.x; Bs[lkq + 1][lrow] = bv.y;
        Bs[lkq + 2][lrow] = bv.z; Bs[lkq + 3][lrow] = bv.w;
        __syncthreads();
#pragma unroll
        for (int k = 0; k < 8; k++) {
            float a[8]; float2 b[4];
            *(float4*)&a[0] = *(const float4*)&As[k][ty * 8];
            *(float4*)&a[4] = *(const float4*)&As[k][ty * 8 + 4];
            *(float4*)&b[0] = *(const float4*)&Bs[k][tx * 8];
            *(float4*)&b[2] = *(const float4*)&Bs[k][tx * 8 + 4];
#pragma unroll
            for (int i = 0; i < 8; i++) {
                float2 a2 = make_float2(a[i], a[i]);
#pragma unroll
                for (int j = 0; j < 4; j++) fma2(acc[i][j], a2, b[j]);
            }
        }
    }

#pragma unroll
    for (int i = 0; i < 8; i++) {
        int r = row0 + ty * 8 + i;
#pragma unroll
        for (int j = 0; j < 4; j++) {
            int c = col0 + tx * 8 + j * 2;
            *(float2*)&g_implicit[(size_t)r * DIMK + c] = acc[i][j];
        }
    }
}

// =====================================================================
// Kernel 1b: c_norm[c] = ||implicit[c]||^2   (one warp per code)
// =====================================================================
__global__ void cnorm_kernel() {
    int c = blockIdx.x * 8 + (threadIdx.x >> 5);
    int lane = threadIdx.x & 31;
    const float* p = g_implicit + (size_t)c * DIMK;
    float s = 0.f;
#pragma unroll
    for (int j = 0; j < DIMK / 32; j++) {
        float v = p[lane + j * 32];
        s = fmaf(v, v, s);
    }
#pragma unroll
    for (int o = 16; o; o >>= 1) s += __shfl_xor_sync(0xffffffffu, s, o);
    if (lane == 0) g_cnorm[c] = s;
}

// =====================================================================
// Kernel 2: fused score-GEMM + argmin.
// Block owns 128 tokens, streams all 8192 codes in 128-wide tiles.
// score[t,c] = cnorm[c] - 2 * x_t . implicit_c ; keep running argmin.
// =====================================================================
__global__ __launch_bounds__(256, 2)
void argmin_kernel(const float* __restrict__ X) {
    __shared__ float Xs[8][132];
    __shared__ float Cs[8][132];
    __shared__ float candV[16][128];
    __shared__ int   candI[16][128];

    const int tid = threadIdx.x;
    const int tx = tid & 15, ty = tid >> 4;
    const int row0 = blockIdx.x * 128;   // token rows

    const int lrow = tid >> 1;
    const int lkq  = (tid & 1) * 4;

    const float* xbase = X + (size_t)(row0 + lrow) * DIMK + lkq;

    float bestv[8]; int besti[8];
#pragma unroll
    for (int i = 0; i < 8; i++) { bestv[i] = 3.4e38f; besti[i] = 0; }

    for (int ct = 0; ct < NCODE / 128; ct++) {
        float2 acc[8][4];
#pragma unroll
        for (int i = 0; i < 8; i++)
#pragma unroll
            for (int j = 0; j < 4; j++) acc[i][j] = make_float2(0.f, 0.f);

        const float* cbase = g_implicit + (size_t)(ct * 128 + lrow) * DIMK + lkq;

        for (int kt = 0; kt < DIMK / 8; kt++) {
            float4 xv = *(const float4*)(xbase + kt * 8);
            float4 cv = *(const float4*)(cbase + kt * 8);
            __syncthreads();
            Xs[lkq + 0][lrow] = xv.x; Xs[lkq + 1][lrow] = xv.y;
            Xs[lkq + 2][lrow] = xv.z; Xs[lkq + 3][lrow] = xv.w;
            Cs[lkq + 0][lrow] = cv.x; Cs[lkq + 1][lrow] = cv.y;
            Cs[lkq + 2][lrow] = cv.z; Cs[lkq + 3][lrow] = cv.w;
            __syncthreads();
#pragma unroll
            for (int k = 0; k < 8; k++) {
                float a[8]; float2 b[4];
                *(float4*)&a[0] = *(const float4*)&Xs[k][ty * 8];
                *(float4*)&a[4] = *(const float4*)&Xs[k][ty * 8 + 4];
                *(float4*)&b[0] = *(const float4*)&Cs[k][tx * 8];
                *(float4*)&b[2] = *(const float4*)&Cs[k][tx * 8 + 4];
#pragma unroll
                for (int i = 0; i < 8; i++) {
                    float2 a2 = make_float2(a[i], a[i]);
#pragma unroll
                    for (int j = 0; j < 4; j++) fma2(acc[i][j], a2, b[j]);
                }
            }
        }

        // epilogue: running argmin (codes processed in increasing index order,
        // strict < keeps the lowest index on ties, matching jnp.argmin)
#pragma unroll
        for (int i = 0; i < 8; i++) {
#pragma unroll
            for (int j = 0; j < 4; j++) {
                int c0 = ct * 128 + tx * 8 + j * 2;
                float s0 = __ldg(&g_cnorm[c0])     - 2.0f * acc[i][j].x;
                float s1 = __ldg(&g_cnorm[c0 + 1]) - 2.0f * acc[i][j].y;
                if (s0 < bestv[i]) { bestv[i] = s0; besti[i] = c0; }
                if (s1 < bestv[i]) { bestv[i] = s1; besti[i] = c0 + 1; }
            }
        }
    }

    // cross-tx reduction per token row
#pragma unroll
    for (int i = 0; i < 8; i++) {
        candV[tx][ty * 8 + i] = bestv[i];
        candI[tx][ty * 8 + i] = besti[i];
    }
    __syncthreads();
    if (tid < 128) {
        float bv = candV[0][tid]; int bi = candI[0][tid];
#pragma unroll
        for (int t = 1; t < 16; t++) {
            float v = candV[t][tid]; int ii = candI[t][tid];
            if (v < bv || (v == bv && ii < bi)) { bv = v; bi = ii; }
        }
        g_indices[row0 + tid] = bi;
    }
}

// =====================================================================
// Kernel 3: gather quantized rows + per-token squared-diff partials.
// One block (128 threads) per token; thread handles one float4.
// =====================================================================
__global__ void gather_kernel(const float* __restrict__ X, float* __restrict__ out,
                              int write_idx) {
    const int t = blockIdx.x;
    const int idx = g_indices[t];
    const float4 q = ((const float4*)(g_implicit + (size_t)idx * DIMK))[threadIdx.x];
    const float4 x = ((const float4*)(X + (size_t)t * DIMK))[threadIdx.x];
    ((float4*)out)[(size_t)t * (DIMK / 4) + threadIdx.x] = q;

    float dx = x.x - q.x, dy = x.y - q.y, dz = x.z - q.z, dw = x.w - q.w;
    float s = dx * dx + dy * dy + dz * dz + dw * dw;
#pragma unroll
    for (int o = 16; o; o >>= 1) s += __shfl_xor_sync(0xffffffffu, s, o);
    __shared__ float ws[4];
    if ((threadIdx.x & 31) == 0) ws[threadIdx.x >> 5] = s;
    __syncthreads();
    if (threadIdx.x == 0) {
        g_partial[t] = ((ws[0] + ws[1]) + (ws[2] + ws[3]));  // fixed order: deterministic
        if (write_idx) out[(size_t)QELEMS + t] = (float)idx;
    }
}

// =====================================================================
// Kernel 4: deterministic loss reduction (fp64 accumulate).
// loss = 0.25*mean((x-q)^2) + mean((x-q)^2) = 1.25 * mean
// =====================================================================
__global__ void loss_kernel(float* __restrict__ out_loss) {
    __shared__ double sh[256];
    double s = 0.0;
    for (int i = threadIdx.x; i < NTOK; i += 256) s += (double)g_partial[i];
    sh[threadIdx.x] = s;
    __syncthreads();
    for (int o = 128; o; o >>= 1) {
        if (threadIdx.x < o) sh[threadIdx.x] += sh[threadIdx.x + o];
        __syncthreads();
    }
    if (threadIdx.x == 0)
        *out_loss = (float)(1.25 * sh[0] / (double)QELEMS);
}

// =====================================================================
extern "C" void kernel_launch(void* const* d_in, const int* in_sizes, int n_in,
                              void* d_out, int out_size) {
    // identify inputs by element count (all sizes distinct)
    const float* x = nullptr; const float* cb = nullptr; const float* W = nullptr;
    for (int i = 0; i < n_in; i++) {
        if (in_sizes[i] == NTOK * DIMK)       x  = (const float*)d_in[i];
        else if (in_sizes[i] == NCODE * DIMK) cb = (const float*)d_in[i];
        else if (in_sizes[i] == DIMK * DIMK)  W  = (const float*)d_in[i];
    }
    float* out = (float*)d_out;

    implicit_gemm_kernel<<<dim3(NCODE / 128, DIMK / 128), 256>>>(cb, W);
    cnorm_kernel<<<NCODE / 8, 256>>>();
    argmin_kernel<<<NTOK / 128, 256>>>(x);

    const int write_idx = (out_size >= QELEMS + NTOK) ? 1 : 0;
    gather_kernel<<<NTOK, 128>>>(x, out, write_idx);

    if (out_size >= QELEMS + NTOK + 1)
        loss_kernel<<<1, 256>>>(out + (size_t)QELEMS + NTOK);
}

// round 5
// speedup vs baseline: 4.1230x; 4.1230x over previous
#include <cuda_runtime.h>
#include <cuda_bf16.h>
#include <cstdint>

// Problem constants
#define DIMK   512
#define NCODE  8192
#define NTOK   16384           // B*N = 4*4096
#define QELEMS (NTOK * DIMK)   // 8388608

#define MARGIN   0.35f
#define SEGCAP   16
#define NSEG     16            // per token: 16 segments x 16 entries

// ---------------- scratch (no allocations allowed) ----------------
__device__ float          g_implicit[(size_t)NCODE * DIMK];    // 16 MB fp32
__device__ __nv_bfloat16  g_implicit_bf[(size_t)NCODE * DIMK]; // 8 MB bf16
__device__ float          g_cnorm[NCODE];
__device__ int            g_indices[NTOK];
__device__ float          g_partial[NTOK];
__device__ int            g_cand[(size_t)NTOK * NSEG * SEGCAP];  // 16 MB
__device__ int            g_candcnt[(size_t)NTOK * NSEG];        // 1 MB

// ===================== helpers =====================
__device__ __forceinline__ uint32_t smem_to_u32(const void* p) {
    uint32_t a;
    asm("{ .reg .u64 t; cvta.to.shared.u64 t, %1; cvt.u32.u64 %0, t; }" : "=r"(a) : "l"(p));
    return a;
}
#define CP_ASYNC16(dst, src) \
    asm volatile("cp.async.ca.shared.global [%0], [%1], 16;" :: "r"(dst), "l"(src))
#define CP_COMMIT() asm volatile("cp.async.commit_group;")
#define CP_WAIT(n)  asm volatile("cp.async.wait_group %0;" :: "n"(n))

__device__ __forceinline__ void ldsm_x4(uint32_t r[4], uint32_t addr) {
    asm volatile("ldmatrix.sync.aligned.m8n8.x4.shared.b16 {%0,%1,%2,%3}, [%4];"
                 : "=r"(r[0]), "=r"(r[1]), "=r"(r[2]), "=r"(r[3]) : "r"(addr));
}
__device__ __forceinline__ void ldsm_x2(uint32_t r[2], uint32_t addr) {
    asm volatile("ldmatrix.sync.aligned.m8n8.x2.shared.b16 {%0,%1}, [%2];"
                 : "=r"(r[0]), "=r"(r[1]) : "r"(addr));
}
__device__ __forceinline__ void mma_bf16(float d[4], const uint32_t a[4], const uint32_t b[2]) {
    asm volatile("mma.sync.aligned.m16n8k16.row.col.f32.bf16.bf16.f32 "
                 "{%0,%1,%2,%3}, {%4,%5,%6,%7}, {%8,%9}, {%0,%1,%2,%3};"
                 : "+f"(d[0]), "+f"(d[1]), "+f"(d[2]), "+f"(d[3])
                 : "r"(a[0]), "r"(a[1]), "r"(a[2]), "r"(a[3]), "r"(b[0]), "r"(b[1]));
}

// packed fp32x2 FMA
__device__ __forceinline__ void fma2(float2 &d, const float2 &a, const float2 &b) {
    asm("fma.rn.f32x2 %0, %1, %2, %0;"
        : "+l"(reinterpret_cast<unsigned long long &>(d))
        : "l"(reinterpret_cast<const unsigned long long &>(a)),
          "l"(reinterpret_cast<const unsigned long long &>(b)));
}

// =====================================================================
// Kernel 1: implicit[c,d] = sum_k codebook[c,k] * W[d,k]  (fp32 exact)
// Also writes bf16 copy for the tensor-core argmin pass.
// =====================================================================
__global__ __launch_bounds__(256, 2)
void implicit_gemm_kernel(const float* __restrict__ CB, const float* __restrict__ W) {
    __shared__ float As[8][132];
    __shared__ float Bs[8][132];

    const int tid = threadIdx.x;
    const int tx = tid & 15, ty = tid >> 4;
    const int row0 = blockIdx.x * 128;
    const int col0 = blockIdx.y * 128;
    const int lrow = tid >> 1;
    const int lkq  = (tid & 1) * 4;

    const float* abase = CB + (size_t)(row0 + lrow) * DIMK + lkq;
    const float* bbase = W  + (size_t)(col0 + lrow) * DIMK + lkq;

    float2 acc[8][4];
#pragma unroll
    for (int i = 0; i < 8; i++)
#pragma unroll
        for (int j = 0; j < 4; j++) acc[i][j] = make_float2(0.f, 0.f);

    for (int kt = 0; kt < DIMK / 8; kt++) {
        float4 av = *(const float4*)(abase + kt * 8);
        float4 bv = *(const float4*)(bbase + kt * 8);
        __syncthreads();
        As[lkq + 0][lrow] = av.x; As[lkq + 1][lrow] = av.y;
        As[lkq + 2][lrow] = av.z; As[lkq + 3][lrow] = av.w;
        Bs[lkq + 0][lrow] = bv.x; Bs[lkq + 1][lrow] = bv.y;
        Bs[lkq + 2][lrow] = bv.z; Bs[lkq + 3][lrow] = bv.w;
        __syncthreads();
#pragma unroll
        for (int k = 0; k < 8; k++) {
            float a[8]; float2 b[4];
            *(float4*)&a[0] = *(const float4*)&As[k][ty * 8];
            *(float4*)&a[4] = *(const float4*)&As[k][ty * 8 + 4];
            *(float4*)&b[0] = *(const float4*)&Bs[k][tx * 8];
            *(float4*)&b[2] = *(const float4*)&Bs[k][tx * 8 + 4];
#pragma unroll
            for (int i = 0; i < 8; i++) {
                float2 a2 = make_float2(a[i], a[i]);
#pragma unroll
                for (int j = 0; j < 4; j++) fma2(acc[i][j], a2, b[j]);
            }
        }
    }

#pragma unroll
    for (int i = 0; i < 8; i++) {
        int r = row0 + ty * 8 + i;
#pragma unroll
        for (int j = 0; j < 4; j++) {
            int c = col0 + tx * 8 + j * 2;
            *(float2*)&g_implicit[(size_t)r * DIMK + c] = acc[i][j];
            __nv_bfloat162 h;
            h.x = __float2bfloat16_rn(acc[i][j].x);
            h.y = __float2bfloat16_rn(acc[i][j].y);
            *(__nv_bfloat162*)&g_implicit_bf[(size_t)r * DIMK + c] = h;
        }
    }
}

// =====================================================================
// Kernel 1b: c_norm[c] = ||implicit[c]||^2
// =====================================================================
__global__ void cnorm_kernel() {
    int c = blockIdx.x * 8 + (threadIdx.x >> 5);
    int lane = threadIdx.x & 31;
    const float* p = g_implicit + (size_t)c * DIMK;
    float s = 0.f;
#pragma unroll
    for (int j = 0; j < DIMK / 32; j++) {
        float v = p[lane + j * 32];
        s = fmaf(v, v, s);
    }
#pragma unroll
    for (int o = 16; o; o >>= 1) s += __shfl_xor_sync(0xffffffffu, s, o);
    if (lane == 0) g_cnorm[c] = s;
}

// =====================================================================
// Kernel 2: warp-level bf16 HMMA score GEMM + candidate collection.
// 128 CTAs x 128 tokens. A (tokens) resident in SMEM bf16, B (codes)
// streamed in 128x64 bf16 chunks with cp.async double buffering.
// 8 warps: 2 (M) x 4 (N); warp tile 64x32; mma.sync m16n8k16.
// Epilogue per 128-code tile: warp-row running min + margin candidates.
// =====================================================================
#define SM_CN 0                       // 8192 floats = 32768 B
#define SM_A  32768                   // 128 rows x 1040 B = 133120 B
#define SM_B  (32768 + 133120)        // 2 x 18432 B
#define SM_TOTAL (SM_B + 2 * 18432)   // 202752 B
#define AROW 1040
#define BROW 144

__global__ __launch_bounds__(256, 1)
void mma_argmin_kernel(const float* __restrict__ X) {
    extern __shared__ char smem[];
    const uint32_t sbase = smem_to_u32(smem);
    const int tid = threadIdx.x, lane = tid & 31, wid = tid >> 5;
    const int warp_m = wid & 1, warp_n = wid >> 1;
    const int row0 = blockIdx.x * 128;

    // cnorm -> SMEM
#pragma unroll
    for (int j = 0; j < 8; j++)
        ((float4*)smem)[tid + j * 256] = ((const float4*)g_cnorm)[tid + j * 256];

    // A-tile: convert 128 token rows fp32 -> bf16 into SMEM
    {
        const int r = tid >> 1;
        const float4* xr = (const float4*)(X + (size_t)(row0 + r) * DIMK) + (tid & 1) * 64;
        char* arow = smem + SM_A + r * AROW + (tid & 1) * 512;
#pragma unroll
        for (int j = 0; j < 32; j++) {
            float4 v0 = xr[2 * j], v1 = xr[2 * j + 1];
            __nv_bfloat162 h0, h1, h2, h3;
            h0.x = __float2bfloat16_rn(v0.x); h0.y = __float2bfloat16_rn(v0.y);
            h1.x = __float2bfloat16_rn(v0.z); h1.y = __float2bfloat16_rn(v0.w);
            h2.x = __float2bfloat16_rn(v1.x); h2.y = __float2bfloat16_rn(v1.y);
            h3.x = __float2bfloat16_rn(v1.z); h3.y = __float2bfloat16_rn(v1.w);
            uint4 pk;
            pk.x = *(uint32_t*)&h0; pk.y = *(uint32_t*)&h1;
            pk.z = *(uint32_t*)&h2; pk.w = *(uint32_t*)&h3;
            *(uint4*)(arow + j * 16) = pk;
        }
    }
    __syncthreads();

    float acc[4][4][4];
#pragma unroll
    for (int mi = 0; mi < 4; mi++)
#pragma unroll
        for (int ni = 0; ni < 4; ni++)
#pragma unroll
            for (int r = 0; r < 4; r++) acc[mi][ni][r] = 0.f;

    float R[8]; int cnt[8];
#pragma unroll
    for (int s = 0; s < 8; s++) { R[s] = 3.4e38f; cnt[s] = 0; }

    // B chunk loader: chunk it -> (ct = it>>3 code tile, kc = it&7 k-chunk)
    const int brow = tid >> 1;
    const int bcol = (tid & 1) * 64;

    // prologue: chunk 0 -> buf 0
    {
        const char* g = (const char*)g_implicit_bf + ((size_t)brow * DIMK) * 2 + bcol;
        uint32_t d = sbase + SM_B + brow * BROW + bcol;
#pragma unroll
        for (int i = 0; i < 4; i++) CP_ASYNC16(d + i * 16, g + i * 16);
        CP_COMMIT();
    }

    for (int it = 0; it < 512; it++) {
        if (it + 1 < 512) {
            const int nct = (it + 1) >> 3, nkc = (it + 1) & 7;
            const char* g = (const char*)g_implicit_bf
                + ((size_t)(nct * 128 + brow) * DIMK + nkc * 64) * 2 + bcol;
            uint32_t d = sbase + SM_B + ((it + 1) & 1) * 18432 + brow * BROW + bcol;
#pragma unroll
            for (int i = 0; i < 4; i++) CP_ASYNC16(d + i * 16, g + i * 16);
            CP_COMMIT();
            CP_WAIT(1);
        } else {
            CP_WAIT(0);
        }
        __syncthreads();

        const uint32_t b0 = sbase + SM_B + (it & 1) * 18432;
        const int kc = it & 7;
#pragma unroll
        for (int kk = 0; kk < 4; kk++) {
            uint32_t a[4][4], b[4][2];
#pragma unroll
            for (int mi = 0; mi < 4; mi++) {
                uint32_t addr = sbase + SM_A
                    + (warp_m * 64 + mi * 16 + (lane & 15)) * AROW
                    + (kc * 64 + kk * 16 + (lane >> 4) * 8) * 2;
                ldsm_x4(a[mi], addr);
            }
#pragma unroll
            for (int ni = 0; ni < 4; ni++) {
                uint32_t addr = b0 + (warp_n * 32 + ni * 8 + (lane & 7)) * BROW
                    + (kk * 16 + ((lane >> 3) & 1) * 8) * 2;
                ldsm_x2(b[ni], addr);
            }
#pragma unroll
            for (int mi = 0; mi < 4; mi++)
#pragma unroll
                for (int ni = 0; ni < 4; ni++)
                    mma_bf16(acc[mi][ni], a[mi], b[ni]);
        }

        if (kc == 7) {
            // ---- epilogue for code tile ct ----
            const int ct = it >> 3;
#pragma unroll
            for (int mi = 0; mi < 4; mi++) {
#pragma unroll
                for (int half = 0; half < 2; half++) {
                    const int slot = mi * 2 + half;
                    float sv[8]; int cv[8];
#pragma unroll
                    for (int ni = 0; ni < 4; ni++) {
#pragma unroll
                        for (int rr = 0; rr < 2; rr++) {
                            int c = ct * 128 + warp_n * 32 + ni * 8 + (lane & 3) * 2 + rr;
                            float cn = *(const float*)(smem + 4 * c);
                            float s = fmaf(-2.f, acc[mi][ni][half * 2 + rr], cn);
                            sv[ni * 2 + rr] = s; cv[ni * 2 + rr] = c;
                            acc[mi][ni][half * 2 + rr] = 0.f;
                        }
                    }
                    float t = sv[0];
#pragma unroll
                    for (int j = 1; j < 8; j++) t = fminf(t, sv[j]);
                    t = fminf(t, __shfl_xor_sync(0xffffffffu, t, 1));
                    t = fminf(t, __shfl_xor_sync(0xffffffffu, t, 2));
                    R[slot] = fminf(R[slot], t);
                    const float thr = R[slot] + MARGIN;
                    const int tok = row0 + warp_m * 64 + mi * 16 + (lane >> 2) + half * 8;
                    int* seg_base = g_cand + (size_t)tok * (NSEG * SEGCAP)
                                    + (warp_n * 4 + (lane & 3)) * SEGCAP;
#pragma unroll
                    for (int j = 0; j < 8; j++) {
                        if (sv[j] < thr) {
                            if (cnt[slot] < SEGCAP) seg_base[cnt[slot]] = cv[j];
                            cnt[slot]++;
                        }
                    }
                }
            }
        }
        __syncthreads();
    }

    // write per-segment counts (cnt > SEGCAP encodes overflow)
#pragma unroll
    for (int mi = 0; mi < 4; mi++)
#pragma unroll
        for (int half = 0; half < 2; half++) {
            const int slot = mi * 2 + half;
            const int tok = row0 + warp_m * 64 + mi * 16 + (lane >> 2) + half * 8;
            const int seg = warp_n * 4 + (lane & 3);
            g_candcnt[(size_t)tok * NSEG + seg] = cnt[slot];
        }
}

// =====================================================================
// Kernel 2b: exact fp32 rescore of candidates -> final argmin.
// One warp per token; overflow (cnt>SEGCAP) -> full exact scan.
// =====================================================================
__global__ __launch_bounds__(256)
void rescue_kernel(const float* __restrict__ X) {
    const int w = threadIdx.x >> 5, lane = threadIdx.x & 31;
    const int t = blockIdx.x * 8 + w;

    const float4* xr = (const float4*)(X + (size_t)t * DIMK) + lane * 4;
    const float4 x0 = xr[0], x1 = xr[1], x2 = xr[2], x3 = xr[3];

    int cnts[NSEG]; bool ovf = false;
#pragma unroll
    for (int s = 0; s < NSEG; s++) {
        int c = g_candcnt[(size_t)t * NSEG + s];
        cnts[s] = c;
        if (c > SEGCAP) ovf = true;
    }

    float bv = 3.4e38f; int bi = 0x7fffffff;

    auto score = [&](int c) {
        const float4* cr = (const float4*)(g_implicit + (size_t)c * DIMK) + lane * 4;
        float4 c0 = cr[0], c1 = cr[1], c2 = cr[2], c3 = cr[3];
        float acc = 0.f;
        acc = fmaf(x0.x, c0.x, acc); acc = fmaf(x0.y, c0.y, acc);
        acc = fmaf(x0.z, c0.z, acc); acc = fmaf(x0.w, c0.w, acc);
        acc = fmaf(x1.x, c1.x, acc); acc = fmaf(x1.y, c1.y, acc);
        acc = fmaf(x1.z, c1.z, acc); acc = fmaf(x1.w, c1.w, acc);
        acc = fmaf(x2.x, c2.x, acc); acc = fmaf(x2.y, c2.y, acc);
        acc = fmaf(x2.z, c2.z, acc); acc = fmaf(x2.w, c2.w, acc);
        acc = fmaf(x3.x, c3.x, acc); acc = fmaf(x3.y, c3.y, acc);
        acc = fmaf(x3.z, c3.z, acc); acc = fmaf(x3.w, c3.w, acc);
#pragma unroll
        for (int o = 16; o; o >>= 1) acc += __shfl_xor_sync(0xffffffffu, acc, o);
        float s = fmaf(-2.0f, acc, __ldg(&g_cnorm[c]));
        if (s < bv || (s == bv && c < bi)) { bv = s; bi = c; }
    };

    if (ovf) {
        for (int c = 0; c < NCODE; c++) score(c);
    } else {
#pragma unroll 1
        for (int s = 0; s < NSEG; s++) {
            const int* seg = g_cand + (size_t)t * (NSEG * SEGCAP) + s * SEGCAP;
            for (int j = 0; j < cnts[s]; j++) score(seg[j]);
        }
    }
    if (lane == 0) g_indices[t] = bi;
}

// =====================================================================
// Kernel 3: gather quantized rows + per-token squared-diff partials.
// =====================================================================
__global__ void gather_kernel(const float* __restrict__ X, float* __restrict__ out,
                              int write_idx) {
    const int t = blockIdx.x;
    const int idx = g_indices[t];
    const float4 q = ((const float4*)(g_implicit + (size_t)idx * DIMK))[threadIdx.x];
    const float4 x = ((const float4*)(X + (size_t)t * DIMK))[threadIdx.x];
    ((float4*)out)[(size_t)t * (DIMK / 4) + threadIdx.x] = q;

    float dx = x.x - q.x, dy = x.y - q.y, dz = x.z - q.z, dw = x.w - q.w;
    float s = dx * dx + dy * dy + dz * dz + dw * dw;
#pragma unroll
    for (int o = 16; o; o >>= 1) s += __shfl_xor_sync(0xffffffffu, s, o);
    __shared__ float ws[4];
    if ((threadIdx.x & 31) == 0) ws[threadIdx.x >> 5] = s;
    __syncthreads();
    if (threadIdx.x == 0) {
        g_partial[t] = ((ws[0] + ws[1]) + (ws[2] + ws[3]));
        if (write_idx) out[(size_t)QELEMS + t] = (float)idx;
    }
}

// =====================================================================
// Kernel 4: deterministic loss reduction (fp64 accumulate).
// =====================================================================
__global__ void loss_kernel(float* __restrict__ out_loss) {
    __shared__ double sh[256];
    double s = 0.0;
    for (int i = threadIdx.x; i < NTOK; i += 256) s += (double)g_partial[i];
    sh[threadIdx.x] = s;
    __syncthreads();
    for (int o = 128; o; o >>= 1) {
        if (threadIdx.x < o) sh[threadIdx.x] += sh[threadIdx.x + o];
        __syncthreads();
    }
    if (threadIdx.x == 0)
        *out_loss = (float)(1.25 * sh[0] / (double)QELEMS);
}

// =====================================================================
extern "C" void kernel_launch(void* const* d_in, const int* in_sizes, int n_in,
                              void* d_out, int out_size) {
    const float* x = nullptr; const float* cb = nullptr; const float* W = nullptr;
    for (int i = 0; i < n_in; i++) {
        if (in_sizes[i] == NTOK * DIMK)       x  = (const float*)d_in[i];
        else if (in_sizes[i] == NCODE * DIMK) cb = (const float*)d_in[i];
        else if (in_sizes[i] == DIMK * DIMK)  W  = (const float*)d_in[i];
    }
    float* out = (float*)d_out;

    implicit_gemm_kernel<<<dim3(NCODE / 128, DIMK / 128), 256>>>(cb, W);
    cnorm_kernel<<<NCODE / 8, 256>>>();

    cudaFuncSetAttribute(mma_argmin_kernel,
                         cudaFuncAttributeMaxDynamicSharedMemorySize, SM_TOTAL);
    mma_argmin_kernel<<<NTOK / 128, 256, SM_TOTAL>>>(x);

    rescue_kernel<<<NTOK / 8, 256>>>(x);

    const int write_idx = (out_size >= QELEMS + NTOK) ? 1 : 0;
    gather_kernel<<<NTOK, 128>>>(x, out, write_idx);

    if (out_size >= QELEMS + NTOK + 1)
        loss_kernel<<<1, 256>>>(out + (size_t)QELEMS + NTOK);
}